// round 6
// baseline (speedup 1.0000x reference)
#include <cuda_runtime.h>
#include <cuda_bf16.h>
#include <cstdint>

#define K_CODES 8192
#define D_DIM   256
#define N_Q     16384
#define HW      1024
#define MQ      128          // queries per CTA
#define CCH     128          // codes per chunk
#define NCHUNKS (K_CODES / CCH)   // 64
#define WIN     2.5e-4f
#define MAXCAND 16

// ---------------- device scratch ----------------
__device__ __nv_bfloat16 g_ztb[(size_t)N_Q * D_DIM];   // z transposed, bf16
__device__ float g_ztf[(size_t)N_Q * D_DIM];           // z transposed, fp32 (exact fixup)
__device__ __nv_bfloat16 g_cbb[(size_t)K_CODES * D_DIM]; // codebook bf16
__device__ float g_c2[K_CODES];
__device__ float g_z2[N_Q];
__device__ int   g_ncand[N_Q];
__device__ int   g_cand[N_Q][MAXCAND];
__device__ int   g_idx[N_Q];

// ---------------- asm helpers ----------------
__device__ __forceinline__ uint32_t sm_u32(const void* p) {
    uint32_t a;
    asm("{ .reg .u64 t; cvta.to.shared.u64 t, %1; cvt.u32.u64 %0, t; }" : "=r"(a) : "l"(p));
    return a;
}
#define CP_ASYNC16(dst, src) \
    asm volatile("cp.async.cg.shared.global [%0], [%1], 16;" :: "r"(dst), "l"(src))
#define CP_COMMIT() asm volatile("cp.async.commit_group;" ::: "memory")
#define CP_WAIT(n)  asm volatile("cp.async.wait_group %0;" :: "n"(n) : "memory")

__device__ __forceinline__ void ldsm_x4(uint32_t& r0, uint32_t& r1, uint32_t& r2,
                                        uint32_t& r3, uint32_t addr) {
    asm volatile("ldmatrix.sync.aligned.m8n8.x4.shared.b16 {%0,%1,%2,%3}, [%4];"
                 : "=r"(r0), "=r"(r1), "=r"(r2), "=r"(r3) : "r"(addr));
}
// NON-trans: B rows are n-major with contiguous k -> plain ldmatrix gives the
// (n=T/4, k=2(T%4)+{0,1}) pairing the row.col B fragment requires.
__device__ __forceinline__ void ldsm_x2(uint32_t& r0, uint32_t& r1, uint32_t addr) {
    asm volatile("ldmatrix.sync.aligned.m8n8.x2.shared.b16 {%0,%1}, [%2];"
                 : "=r"(r0), "=r"(r1) : "r"(addr));
}
__device__ __forceinline__ void mma_bf16(float& d0, float& d1, float& d2, float& d3,
                                         uint32_t a0, uint32_t a1, uint32_t a2, uint32_t a3,
                                         uint32_t b0, uint32_t b1) {
    asm volatile("mma.sync.aligned.m16n8k16.row.col.f32.bf16.bf16.f32 "
                 "{%0,%1,%2,%3},{%4,%5,%6,%7},{%8,%9},{%0,%1,%2,%3};"
                 : "+f"(d0), "+f"(d1), "+f"(d2), "+f"(d3)
                 : "r"(a0), "r"(a1), "r"(a2), "r"(a3), "r"(b0), "r"(b1));
}
// swizzled byte offset within a [row][256 bf16] tile (512B rows, 16B units)
__device__ __forceinline__ uint32_t swz(uint32_t r, uint32_t u) {
    return r * 512u + ((u ^ (r & 7u)) << 4);
}

// ---------------- prep kernels ----------------
__global__ void k_prep_cb(const float* __restrict__ cb) {
    int i = blockIdx.x * blockDim.x + threadIdx.x;  // per float4
    float4 v = ((const float4*)cb)[i];
    ((__nv_bfloat162*)g_cbb)[i * 2] =
        __nv_bfloat162(__float2bfloat16(v.x), __float2bfloat16(v.y));
    ((__nv_bfloat162*)g_cbb)[i * 2 + 1] =
        __nv_bfloat162(__float2bfloat16(v.z), __float2bfloat16(v.w));
}

// exact c2 (proven round-1, verbatim)
__global__ void k_c2(const float* __restrict__ cb) {
    int w = (blockIdx.x * blockDim.x + threadIdx.x) >> 5;
    int lane = threadIdx.x & 31;
    if (w >= K_CODES) return;
    float s = 0.f;
#pragma unroll
    for (int i = 0; i < 8; i++) {
        float v = cb[(size_t)w * D_DIM + lane + i * 32];
        s = __fadd_rn(s, __fmul_rn(v, v));
    }
#pragma unroll
    for (int o = 16; o; o >>= 1) s = __fadd_rn(s, __shfl_xor_sync(0xffffffffu, s, o));
    if (lane == 0) g_c2[w] = s;
}

// exact z2 (proven round-1, verbatim)
__global__ void k_z2(const float* __restrict__ z) {
    int q = blockIdx.x * blockDim.x + threadIdx.x;
    int b = q >> 10, hw = q & 1023;
    const float* p = z + (size_t)b * (D_DIM * HW) + hw;
    float s = 0.f;
    for (int d = 0; d < D_DIM; d++) {
        float v = p[(size_t)d * HW];
        s = __fadd_rn(s, __fmul_rn(v, v));
    }
    g_z2[q] = s;
}

// NCHW -> [q][d] fp32 + bf16
__global__ void k_prep_z(const float* __restrict__ z) {
    __shared__ float tile[32][33];
    int b = blockIdx.z, d0 = blockIdx.y * 32, h0 = blockIdx.x * 32;
    int tx = threadIdx.x, ty = threadIdx.y;  // 32 x 8
#pragma unroll
    for (int j = 0; j < 32; j += 8)
        tile[ty + j][tx] = z[(size_t)(b * D_DIM + d0 + ty + j) * HW + h0 + tx];
    __syncthreads();
#pragma unroll
    for (int j = 0; j < 32; j += 8) {
        int q = b * HW + h0 + ty + j, d = d0 + tx;
        float vv = tile[tx][ty + j];
        g_ztf[(size_t)q * D_DIM + d] = vv;
        g_ztb[(size_t)q * D_DIM + d] = __float2bfloat16(vv);
    }
}

// ---------------- main HMMA kernel ----------------
// smem: A 64KB | B0 64KB | B1 64KB  (+1KB align pad)
__global__ __launch_bounds__(256, 1) void k_mma() {
    extern __shared__ char sraw[];
    uint32_t raw32 = sm_u32(sraw);
    uint32_t pad = (1024u - (raw32 & 1023u)) & 1023u;
    char* base = sraw + pad;
    const uint32_t sA = raw32 + pad;
    const uint32_t sB0 = sA + 65536u, sB1 = sB0 + 65536u;

    const int t = threadIdx.x, lane = t & 31, w = t >> 5;
    const int mw = w >> 2;          // 0..1 : query half (64 rows)
    const int nw = w & 3;           // 0..3 : code quarter within chunk (32 cols)
    const int q0 = blockIdx.x * MQ;

    // issue B chunk 0
    {
        const char* src = (const char*)(g_cbb);
#pragma unroll
        for (int i = 0; i < 16; i++) {
            int idx = i * 256 + t;
            uint32_t r = (uint32_t)(idx >> 5), u = (uint32_t)(idx & 31);
            CP_ASYNC16(sB0 + swz(r, u), src + (size_t)idx * 16);
        }
        CP_COMMIT();
    }
    // load A tile (128 q x 256 d bf16, swizzled)
    {
        const int4* src = (const int4*)(g_ztb + (size_t)q0 * D_DIM);
#pragma unroll
        for (int i = 0; i < 16; i++) {
            int idx = i * 256 + t;
            uint32_t r = (uint32_t)(idx >> 5), u = (uint32_t)(idx & 31);
            *(int4*)(base + swz(r, u)) = src[idx];
        }
    }

    // per-thread top-2 per row-slot (8 slots: mi*2 + half)
    float v1[8], v2[8];
    int   k1[8], k2[8];
#pragma unroll
    for (int i = 0; i < 8; i++) {
        v1[i] = __int_as_float(0x7f800000); v2[i] = __int_as_float(0x7f800000);
        k1[i] = 0x7fffffff; k2[i] = 0x7fffffff;
    }

    // precompute A row bases (per mi), row fixed across k-iters
    uint32_t aRow[4], aR7[4];
#pragma unroll
    for (int mi = 0; mi < 4; mi++) {
        uint32_t r = (uint32_t)(mw * 64 + mi * 16 + (lane & 15));
        aRow[mi] = sA + r * 512u;
        aR7[mi] = r & 7u;
    }
    const uint32_t aU = (uint32_t)(lane >> 4);          // +0 or +1 16B unit (k 8-15)
    const uint32_t bRl = (uint32_t)(nw * 32 + (lane & 7));  // code row base (per ni add ni*8)
    const uint32_t bU = (uint32_t)((lane >> 3) & 1);    // lanes 8-15: k-unit +1 (b1 = k+8)

    for (int ch = 0; ch < NCHUNKS; ch++) {
        // issue next chunk, then wait for current
        if (ch + 1 < NCHUNKS) {
            uint32_t dstB = ((ch + 1) & 1) ? sB1 : sB0;
            const char* src = (const char*)(g_cbb + (size_t)(ch + 1) * CCH * D_DIM);
#pragma unroll
            for (int i = 0; i < 16; i++) {
                int idx = i * 256 + t;
                uint32_t r = (uint32_t)(idx >> 5), u = (uint32_t)(idx & 31);
                CP_ASYNC16(dstB + swz(r, u), src + (size_t)idx * 16);
            }
            CP_COMMIT();
            CP_WAIT(1);
        } else {
            CP_WAIT(0);
        }
        __syncthreads();

        const uint32_t sB = (ch & 1) ? sB1 : sB0;
        float acc[4][4][4];
#pragma unroll
        for (int mi = 0; mi < 4; mi++)
#pragma unroll
            for (int ni = 0; ni < 4; ni++)
#pragma unroll
                for (int e = 0; e < 4; e++) acc[mi][ni][e] = 0.f;

#pragma unroll
        for (int kk = 0; kk < 16; kk++) {
            uint32_t au = (uint32_t)(kk * 2) + aU;
            uint32_t af[4][4];
#pragma unroll
            for (int mi = 0; mi < 4; mi++)
                ldsm_x4(af[mi][0], af[mi][1], af[mi][2], af[mi][3],
                        aRow[mi] + ((au ^ aR7[mi]) << 4));
            uint32_t bu = (uint32_t)(kk * 2) + bU;
            uint32_t bf[4][2];
#pragma unroll
            for (int ni = 0; ni < 4; ni++) {
                uint32_t r = bRl + (uint32_t)(ni * 8);
                ldsm_x2(bf[ni][0], bf[ni][1], sB + r * 512u + ((bu ^ (r & 7u)) << 4));
            }
#pragma unroll
            for (int mi = 0; mi < 4; mi++)
#pragma unroll
                for (int ni = 0; ni < 4; ni++)
                    mma_bf16(acc[mi][ni][0], acc[mi][ni][1], acc[mi][ni][2], acc[mi][ni][3],
                             af[mi][0], af[mi][1], af[mi][2], af[mi][3],
                             bf[ni][0], bf[ni][1]);
        }

        // epilogue: s = c2 - 2*dot, fold into top-2
        const int kb = ch * CCH + nw * 32 + (lane & 3) * 2;
#pragma unroll
        for (int ni = 0; ni < 4; ni++) {
            float2 c2v = *(const float2*)(g_c2 + kb + ni * 8);
            int c0 = kb + ni * 8, c1 = c0 + 1;
#pragma unroll
            for (int mi = 0; mi < 4; mi++) {
#pragma unroll
                for (int half = 0; half < 2; half++) {
                    int sl = mi * 2 + half;
                    float s0 = __fmaf_rn(-2.f, acc[mi][ni][half * 2], c2v.x);
                    float s1 = __fmaf_rn(-2.f, acc[mi][ni][half * 2 + 1], c2v.y);
                    if (s0 < v1[sl]) { v2[sl] = v1[sl]; k2[sl] = k1[sl]; v1[sl] = s0; k1[sl] = c0; }
                    else if (s0 < v2[sl]) { v2[sl] = s0; k2[sl] = c0; }
                    if (s1 < v1[sl]) { v2[sl] = v1[sl]; k2[sl] = k1[sl]; v1[sl] = s1; k1[sl] = c1; }
                    else if (s1 < v2[sl]) { v2[sl] = s1; k2[sl] = c1; }
                }
            }
        }
        __syncthreads();
    }

    // ---- merge candidates: cand[q_local][32] in B0 region (free: last chunk used B1) ----
    float2* cand = (float2*)(base + 65536);
#pragma unroll
    for (int sl = 0; sl < 8; sl++) {
        int ql = mw * 64 + (sl >> 1) * 16 + (sl & 1) * 8 + (lane >> 2);
        int e = nw * 8 + (lane & 3) * 2;
        cand[ql * 32 + e]     = make_float2(v1[sl], __int_as_float(k1[sl]));
        cand[ql * 32 + e + 1] = make_float2(v2[sl], __int_as_float(k2[sl]));
    }
    __syncthreads();
    if (t < MQ) {
        float m1 = __int_as_float(0x7f800000);
#pragma unroll
        for (int e = 0; e < 32; e++) m1 = fminf(m1, cand[t * 32 + e].x);
        float lim = m1 + WIN;
        int overflow = 0;
#pragma unroll
        for (int e = 1; e < 32; e += 2) overflow |= (cand[t * 32 + e].x <= lim);
        int q = q0 + t;
        if (overflow) {
            g_ncand[q] = -1;
        } else {
            int n = 0;
#pragma unroll
            for (int e = 0; e < 32; e += 2) {
                float2 c = cand[t * 32 + e];
                if (c.x <= lim) g_cand[q][n++] = __float_as_int(c.y);
            }
            g_ncand[q] = n;
        }
    }
}

// ---------------- exact fixup ----------------
__device__ __forceinline__ float exact_dist(int q, int k, const float* __restrict__ cb) {
    const float* zr = g_ztf + (size_t)q * D_DIM;
    const float* cr = cb + (size_t)k * D_DIM;
    float acc = 0.f;
#pragma unroll 8
    for (int d = 0; d < D_DIM; d++) acc = __fmaf_rn(zr[d], cr[d], acc);
    return __fadd_rn(__fsub_rn(g_z2[q], __fmul_rn(2.0f, acc)), g_c2[k]);
}

__global__ void k_fixup(const float* __restrict__ cb) {
    int q = (blockIdx.x * blockDim.x + threadIdx.x) >> 5;
    int lane = threadIdx.x & 31;
    if (q >= N_Q) return;
    int n = g_ncand[q];
    float bv = __int_as_float(0x7f800000); int bk = 0x7fffffff;
    if (n < 0) {
        for (int k = lane; k < K_CODES; k += 32) {
            float d = exact_dist(q, k, cb);
            if (d < bv || (d == bv && k < bk)) { bv = d; bk = k; }
        }
    } else if (lane < n) {
        bk = g_cand[q][lane];
        bv = exact_dist(q, bk, cb);
    }
#pragma unroll
    for (int o = 16; o; o >>= 1) {
        float ov = __shfl_xor_sync(0xffffffffu, bv, o);
        int   ok = __shfl_xor_sync(0xffffffffu, bk, o);
        if (ov < bv || (ov == bv && ok < bk)) { bv = ov; bk = ok; }
    }
    if (lane == 0) g_idx[q] = bk;
}

// ---------------- z_q writer (exact straight-through arithmetic) ----------------
__global__ __launch_bounds__(256) void k_zq(const float* __restrict__ z,
                                            const float* __restrict__ cb,
                                            float* __restrict__ out, int write_idx) {
    __shared__ int sidx[MQ];
    int t = threadIdx.x, qb = blockIdx.x * MQ;
    int b = qb >> 10, hw0 = qb & 1023;
    if (t < MQ) {
        int ix = g_idx[qb + t];
        sidx[t] = ix;
        if (write_idx) out[(size_t)N_Q * D_DIM + qb + t] = (float)ix;
    }
    __syncthreads();
#pragma unroll 4
    for (int i = 0; i < 128; i++) {
        int idx2 = t + i * 256;
        int d = idx2 >> 7, q = idx2 & 127;
        float zv = z[(size_t)b * (D_DIM * HW) + (size_t)d * HW + hw0 + q];
        float cv = cb[(size_t)sidx[q] * D_DIM + d];
        out[(size_t)b * (D_DIM * HW) + (size_t)d * HW + hw0 + q] =
            __fadd_rn(zv, __fsub_rn(cv, zv));
    }
}

// ---------------- launch ----------------
extern "C" void kernel_launch(void* const* d_in, const int* in_sizes, int n_in,
                              void* d_out, int out_size) {
    const float* z_e = (const float*)d_in[0];
    const float* cb  = (const float*)d_in[1];
    float* out = (float*)d_out;

    static bool done = false;
    const size_t smem = 3 * 65536 + 1024;  // A + 2 B stages + align pad = 197632
    if (!done) {
        cudaFuncSetAttribute(k_mma, cudaFuncAttributeMaxDynamicSharedMemorySize, (int)smem);
        done = true;
    }
    int write_idx = (out_size >= (int)(N_Q * D_DIM + N_Q)) ? 1 : 0;

    k_prep_cb<<<(K_CODES * D_DIM / 4) / 256, 256>>>(cb);
    k_c2<<<(K_CODES * 32) / 256, 256>>>(cb);
    k_prep_z<<<dim3(HW / 32, D_DIM / 32, 16), dim3(32, 8)>>>(z_e);
    k_z2<<<N_Q / 256, 256>>>(z_e);
    k_mma<<<N_Q / MQ, 256, smem>>>();
    k_fixup<<<(N_Q * 32) / 256, 256>>>(cb);
    k_zq<<<N_Q / MQ, 256>>>(z_e, cb, out, write_idx);
}

// round 8
// speedup vs baseline: 6.6937x; 6.6937x over previous
#include <cuda_runtime.h>
#include <cuda_bf16.h>
#include <cstdint>

#define K_CODES 8192
#define D_DIM   256
#define N_Q     16384
#define HW      1024
#define MQ      128          // queries per CTA
#define CCH     128          // codes per chunk
#define NCHUNKS (K_CODES / CCH)   // 64
#define WIN     2e-4f
#define MAXCAND 16

// ---------------- device scratch ----------------
__device__ __nv_bfloat16 g_ztb[(size_t)N_Q * D_DIM];   // z transposed, bf16
__device__ float g_ztf[(size_t)N_Q * D_DIM];           // z transposed, fp32 (exact fixup)
__device__ __nv_bfloat16 g_cbb[(size_t)K_CODES * D_DIM]; // codebook bf16
__device__ float g_c2[K_CODES];
__device__ float g_z2[N_Q];
__device__ int   g_ncand[N_Q];
__device__ int   g_cand[N_Q][MAXCAND];
__device__ int   g_idx[N_Q];

// ---------------- asm helpers ----------------
__device__ __forceinline__ uint32_t sm_u32(const void* p) {
    uint32_t a;
    asm("{ .reg .u64 t; cvta.to.shared.u64 t, %1; cvt.u32.u64 %0, t; }" : "=r"(a) : "l"(p));
    return a;
}
#define CP_ASYNC16(dst, src) \
    asm volatile("cp.async.cg.shared.global [%0], [%1], 16;" :: "r"(dst), "l"(src))
#define CP_COMMIT() asm volatile("cp.async.commit_group;" ::: "memory")
#define CP_WAIT(n)  asm volatile("cp.async.wait_group %0;" :: "n"(n) : "memory")

__device__ __forceinline__ void ldsm_x4(uint32_t& r0, uint32_t& r1, uint32_t& r2,
                                        uint32_t& r3, uint32_t addr) {
    asm volatile("ldmatrix.sync.aligned.m8n8.x4.shared.b16 {%0,%1,%2,%3}, [%4];"
                 : "=r"(r0), "=r"(r1), "=r"(r2), "=r"(r3) : "r"(addr));
}
// NON-trans: B rows are n-major with contiguous k -> plain ldmatrix gives the
// (n=T/4, k=2(T%4)+{0,1}) pairing the row.col B fragment requires.
__device__ __forceinline__ void ldsm_x2(uint32_t& r0, uint32_t& r1, uint32_t addr) {
    asm volatile("ldmatrix.sync.aligned.m8n8.x2.shared.b16 {%0,%1}, [%2];"
                 : "=r"(r0), "=r"(r1) : "r"(addr));
}
__device__ __forceinline__ void mma_bf16(float& d0, float& d1, float& d2, float& d3,
                                         uint32_t a0, uint32_t a1, uint32_t a2, uint32_t a3,
                                         uint32_t b0, uint32_t b1) {
    asm volatile("mma.sync.aligned.m16n8k16.row.col.f32.bf16.bf16.f32 "
                 "{%0,%1,%2,%3},{%4,%5,%6,%7},{%8,%9},{%0,%1,%2,%3};"
                 : "+f"(d0), "+f"(d1), "+f"(d2), "+f"(d3)
                 : "r"(a0), "r"(a1), "r"(a2), "r"(a3), "r"(b0), "r"(b1));
}
// swizzled byte offset within a [row][256 bf16] tile (512B rows, 16B units)
__device__ __forceinline__ uint32_t swz(uint32_t r, uint32_t u) {
    return r * 512u + ((u ^ (r & 7u)) << 4);
}

// ---------------- prep kernels ----------------
__global__ void k_prep_cb(const float* __restrict__ cb) {
    int i = blockIdx.x * blockDim.x + threadIdx.x;  // per float4
    float4 v = ((const float4*)cb)[i];
    ((__nv_bfloat162*)g_cbb)[i * 2] =
        __nv_bfloat162(__float2bfloat16(v.x), __float2bfloat16(v.y));
    ((__nv_bfloat162*)g_cbb)[i * 2 + 1] =
        __nv_bfloat162(__float2bfloat16(v.z), __float2bfloat16(v.w));
}

// exact c2 (proven round-1, verbatim)
__global__ void k_c2(const float* __restrict__ cb) {
    int w = (blockIdx.x * blockDim.x + threadIdx.x) >> 5;
    int lane = threadIdx.x & 31;
    if (w >= K_CODES) return;
    float s = 0.f;
#pragma unroll
    for (int i = 0; i < 8; i++) {
        float v = cb[(size_t)w * D_DIM + lane + i * 32];
        s = __fadd_rn(s, __fmul_rn(v, v));
    }
#pragma unroll
    for (int o = 16; o; o >>= 1) s = __fadd_rn(s, __shfl_xor_sync(0xffffffffu, s, o));
    if (lane == 0) g_c2[w] = s;
}

// exact z2 (proven round-1, verbatim)
__global__ void k_z2(const float* __restrict__ z) {
    int q = blockIdx.x * blockDim.x + threadIdx.x;
    int b = q >> 10, hw = q & 1023;
    const float* p = z + (size_t)b * (D_DIM * HW) + hw;
    float s = 0.f;
    for (int d = 0; d < D_DIM; d++) {
        float v = p[(size_t)d * HW];
        s = __fadd_rn(s, __fmul_rn(v, v));
    }
    g_z2[q] = s;
}

// NCHW -> [q][d] fp32 + bf16
__global__ void k_prep_z(const float* __restrict__ z) {
    __shared__ float tile[32][33];
    int b = blockIdx.z, d0 = blockIdx.y * 32, h0 = blockIdx.x * 32;
    int tx = threadIdx.x, ty = threadIdx.y;  // 32 x 8
#pragma unroll
    for (int j = 0; j < 32; j += 8)
        tile[ty + j][tx] = z[(size_t)(b * D_DIM + d0 + ty + j) * HW + h0 + tx];
    __syncthreads();
#pragma unroll
    for (int j = 0; j < 32; j += 8) {
        int q = b * HW + h0 + ty + j, d = d0 + tx;
        float vv = tile[tx][ty + j];
        g_ztf[(size_t)q * D_DIM + d] = vv;
        g_ztb[(size_t)q * D_DIM + d] = __float2bfloat16(vv);
    }
}

// ---------------- main HMMA kernel ----------------
// smem: A 64KB | B0 64KB | B1 64KB  (+1KB align pad)
__global__ __launch_bounds__(256, 1) void k_mma() {
    extern __shared__ char sraw[];
    uint32_t raw32 = sm_u32(sraw);
    uint32_t pad = (1024u - (raw32 & 1023u)) & 1023u;
    char* base = sraw + pad;
    const uint32_t sA = raw32 + pad;
    const uint32_t sB0 = sA + 65536u, sB1 = sB0 + 65536u;

    const int t = threadIdx.x, lane = t & 31, w = t >> 5;
    const int mw = w >> 2;          // 0..1 : query half (64 rows)
    const int nw = w & 3;           // 0..3 : code quarter within chunk (32 cols)
    const int q0 = blockIdx.x * MQ;

    // issue B chunk 0
    {
        const char* src = (const char*)(g_cbb);
#pragma unroll
        for (int i = 0; i < 16; i++) {
            int idx = i * 256 + t;
            uint32_t r = (uint32_t)(idx >> 5), u = (uint32_t)(idx & 31);
            CP_ASYNC16(sB0 + swz(r, u), src + (size_t)idx * 16);
        }
        CP_COMMIT();
    }
    // load A tile (128 q x 256 d bf16, swizzled)
    {
        const int4* src = (const int4*)(g_ztb + (size_t)q0 * D_DIM);
#pragma unroll
        for (int i = 0; i < 16; i++) {
            int idx = i * 256 + t;
            uint32_t r = (uint32_t)(idx >> 5), u = (uint32_t)(idx & 31);
            *(int4*)(base + swz(r, u)) = src[idx];
        }
    }

    // per-thread top-3 per row-slot (8 slots: mi*2 + half)
    float v1[8], v2[8], v3[8];
    int   k1[8], k2[8], k3[8];
#pragma unroll
    for (int i = 0; i < 8; i++) {
        v1[i] = __int_as_float(0x7f800000); v2[i] = v1[i]; v3[i] = v1[i];
        k1[i] = 0x7fffffff; k2[i] = k1[i]; k3[i] = k1[i];
    }

    // precompute A row bases (per mi), row fixed across k-iters
    uint32_t aRow[4], aR7[4];
#pragma unroll
    for (int mi = 0; mi < 4; mi++) {
        uint32_t r = (uint32_t)(mw * 64 + mi * 16 + (lane & 15));
        aRow[mi] = sA + r * 512u;
        aR7[mi] = r & 7u;
    }
    const uint32_t aU = (uint32_t)(lane >> 4);          // +0 or +1 16B unit (k 8-15)
    const uint32_t bRl = (uint32_t)(nw * 32 + (lane & 7));  // code row base (per ni add ni*8)
    const uint32_t bU = (uint32_t)((lane >> 3) & 1);    // lanes 8-15: k-unit +1 (b1 = k+8)

    for (int ch = 0; ch < NCHUNKS; ch++) {
        // issue next chunk, then wait for current
        if (ch + 1 < NCHUNKS) {
            uint32_t dstB = ((ch + 1) & 1) ? sB1 : sB0;
            const char* src = (const char*)(g_cbb + (size_t)(ch + 1) * CCH * D_DIM);
#pragma unroll
            for (int i = 0; i < 16; i++) {
                int idx = i * 256 + t;
                uint32_t r = (uint32_t)(idx >> 5), u = (uint32_t)(idx & 31);
                CP_ASYNC16(dstB + swz(r, u), src + (size_t)idx * 16);
            }
            CP_COMMIT();
            CP_WAIT(1);
        } else {
            CP_WAIT(0);
        }
        __syncthreads();

        const uint32_t sB = (ch & 1) ? sB1 : sB0;
        float acc[4][4][4];
#pragma unroll
        for (int mi = 0; mi < 4; mi++)
#pragma unroll
            for (int ni = 0; ni < 4; ni++)
#pragma unroll
                for (int e = 0; e < 4; e++) acc[mi][ni][e] = 0.f;

#pragma unroll
        for (int kk = 0; kk < 16; kk++) {
            uint32_t au = (uint32_t)(kk * 2) + aU;
            uint32_t af[4][4];
#pragma unroll
            for (int mi = 0; mi < 4; mi++)
                ldsm_x4(af[mi][0], af[mi][1], af[mi][2], af[mi][3],
                        aRow[mi] + ((au ^ aR7[mi]) << 4));
            uint32_t bu = (uint32_t)(kk * 2) + bU;
            uint32_t bf[4][2];
#pragma unroll
            for (int ni = 0; ni < 4; ni++) {
                uint32_t r = bRl + (uint32_t)(ni * 8);
                ldsm_x2(bf[ni][0], bf[ni][1], sB + r * 512u + ((bu ^ (r & 7u)) << 4));
            }
#pragma unroll
            for (int mi = 0; mi < 4; mi++)
#pragma unroll
                for (int ni = 0; ni < 4; ni++)
                    mma_bf16(acc[mi][ni][0], acc[mi][ni][1], acc[mi][ni][2], acc[mi][ni][3],
                             af[mi][0], af[mi][1], af[mi][2], af[mi][3],
                             bf[ni][0], bf[ni][1]);
        }

        // epilogue: s = c2 - 2*dot, fold into per-slot top-3 (codes ascending)
        const int kb = ch * CCH + nw * 32 + (lane & 3) * 2;
#pragma unroll
        for (int ni = 0; ni < 4; ni++) {
            float2 c2v = *(const float2*)(g_c2 + kb + ni * 8);
            int c0 = kb + ni * 8, c1 = c0 + 1;
#pragma unroll
            for (int mi = 0; mi < 4; mi++) {
#pragma unroll
                for (int half = 0; half < 2; half++) {
                    int sl = mi * 2 + half;
                    float s0 = __fmaf_rn(-2.f, acc[mi][ni][half * 2], c2v.x);
                    float s1 = __fmaf_rn(-2.f, acc[mi][ni][half * 2 + 1], c2v.y);
                    if (s0 < v3[sl]) {
                        if (s0 < v1[sl]) { v3[sl]=v2[sl];k3[sl]=k2[sl]; v2[sl]=v1[sl];k2[sl]=k1[sl]; v1[sl]=s0;k1[sl]=c0; }
                        else if (s0 < v2[sl]) { v3[sl]=v2[sl];k3[sl]=k2[sl]; v2[sl]=s0;k2[sl]=c0; }
                        else { v3[sl]=s0;k3[sl]=c0; }
                    }
                    if (s1 < v3[sl]) {
                        if (s1 < v1[sl]) { v3[sl]=v2[sl];k3[sl]=k2[sl]; v2[sl]=v1[sl];k2[sl]=k1[sl]; v1[sl]=s1;k1[sl]=c1; }
                        else if (s1 < v2[sl]) { v3[sl]=v2[sl];k3[sl]=k2[sl]; v2[sl]=s1;k2[sl]=c1; }
                        else { v3[sl]=s1;k3[sl]=c1; }
                    }
                }
            }
        }
        __syncthreads();
    }

    // ---- merge candidates: cand[q_local][48] in B0 region (48*8*128 = 49KB) ----
    float2* cand = (float2*)(base + 65536);
#pragma unroll
    for (int sl = 0; sl < 8; sl++) {
        int ql = mw * 64 + (sl >> 1) * 16 + (sl & 1) * 8 + (lane >> 2);
        int e = nw * 12 + (lane & 3) * 3;
        cand[ql * 48 + e]     = make_float2(v1[sl], __int_as_float(k1[sl]));
        cand[ql * 48 + e + 1] = make_float2(v2[sl], __int_as_float(k2[sl]));
        cand[ql * 48 + e + 2] = make_float2(v3[sl], __int_as_float(k3[sl]));
    }
    __syncthreads();
    if (t < MQ) {
        float m1 = __int_as_float(0x7f800000);
#pragma unroll
        for (int e = 0; e < 48; e++) m1 = fminf(m1, cand[t * 48 + e].x);
        float lim = m1 + WIN;
        // overflow only if some slot's 3rd-best is in window (a 4th could be hidden)
        int overflow = 0;
#pragma unroll
        for (int e = 2; e < 48; e += 3) overflow |= (cand[t * 48 + e].x <= lim);
        int q = q0 + t;
        int n = 0;
        if (!overflow) {
#pragma unroll
            for (int e = 0; e < 48; e++) {
                if ((e % 3) == 2) continue;  // v3 not in window (checked above)
                float2 c = cand[t * 48 + e];
                if (c.x <= lim && n < MAXCAND) g_cand[q][n++] = __float_as_int(c.y);
                else if (c.x <= lim) overflow = 1;  // cap exceeded -> safe fallback
            }
        }
        g_ncand[q] = overflow ? -1 : n;
    }
}

// ---------------- exact fixup ----------------
__device__ __forceinline__ float exact_dist(int q, int k, const float* __restrict__ cb) {
    const float* zr = g_ztf + (size_t)q * D_DIM;
    const float* cr = cb + (size_t)k * D_DIM;
    float acc = 0.f;
#pragma unroll 8
    for (int d = 0; d < D_DIM; d++) acc = __fmaf_rn(zr[d], cr[d], acc);
    return __fadd_rn(__fsub_rn(g_z2[q], __fmul_rn(2.0f, acc)), g_c2[k]);
}

__global__ void k_fixup(const float* __restrict__ cb) {
    int q = (blockIdx.x * blockDim.x + threadIdx.x) >> 5;
    int lane = threadIdx.x & 31;
    if (q >= N_Q) return;
    int n = g_ncand[q];
    float bv = __int_as_float(0x7f800000); int bk = 0x7fffffff;
    if (n < 0) {
        // safety net: exact full rescan (statistically unreachable now)
        for (int k = lane; k < K_CODES; k += 32) {
            float d = exact_dist(q, k, cb);
            if (d < bv || (d == bv && k < bk)) { bv = d; bk = k; }
        }
    } else if (lane < n) {
        bk = g_cand[q][lane];
        bv = exact_dist(q, bk, cb);
    }
#pragma unroll
    for (int o = 16; o; o >>= 1) {
        float ov = __shfl_xor_sync(0xffffffffu, bv, o);
        int   ok = __shfl_xor_sync(0xffffffffu, bk, o);
        if (ov < bv || (ov == bv && ok < bk)) { bv = ov; bk = ok; }
    }
    if (lane == 0) g_idx[q] = bk;
}

// ---------------- z_q writer (exact straight-through arithmetic) ----------------
__global__ __launch_bounds__(256) void k_zq(const float* __restrict__ z,
                                            const float* __restrict__ cb,
                                            float* __restrict__ out, int write_idx) {
    __shared__ int sidx[MQ];
    int t = threadIdx.x, qb = blockIdx.x * MQ;
    int b = qb >> 10, hw0 = qb & 1023;
    if (t < MQ) {
        int ix = g_idx[qb + t];
        sidx[t] = ix;
        if (write_idx) out[(size_t)N_Q * D_DIM + qb + t] = (float)ix;
    }
    __syncthreads();
#pragma unroll 4
    for (int i = 0; i < 128; i++) {
        int idx2 = t + i * 256;
        int d = idx2 >> 7, q = idx2 & 127;
        float zv = z[(size_t)b * (D_DIM * HW) + (size_t)d * HW + hw0 + q];
        float cv = cb[(size_t)sidx[q] * D_DIM + d];
        out[(size_t)b * (D_DIM * HW) + (size_t)d * HW + hw0 + q] =
            __fadd_rn(zv, __fsub_rn(cv, zv));
    }
}

// ---------------- launch ----------------
extern "C" void kernel_launch(void* const* d_in, const int* in_sizes, int n_in,
                              void* d_out, int out_size) {
    const float* z_e = (const float*)d_in[0];
    const float* cb  = (const float*)d_in[1];
    float* out = (float*)d_out;

    const size_t smem = 3 * 65536 + 1024;  // A + 2 B stages + align pad = 197632
    cudaFuncSetAttribute(k_mma, cudaFuncAttributeMaxDynamicSharedMemorySize, (int)smem);
    int write_idx = (out_size >= (int)(N_Q * D_DIM + N_Q)) ? 1 : 0;

    k_prep_cb<<<(K_CODES * D_DIM / 4) / 256, 256>>>(cb);
    k_c2<<<(K_CODES * 32) / 256, 256>>>(cb);
    k_prep_z<<<dim3(HW / 32, D_DIM / 32, 16), dim3(32, 8)>>>(z_e);
    k_z2<<<N_Q / 256, 256>>>(z_e);
    k_mma<<<N_Q / MQ, 256, smem>>>();
    k_fixup<<<(N_Q * 32) / 256, 256>>>(cb);
    k_zq<<<N_Q / MQ, 256>>>(z_e, cb, out, write_idx);
}

// round 10
// speedup vs baseline: 6.7243x; 1.0046x over previous
#include <cuda_runtime.h>
#include <cuda_bf16.h>
#include <cstdint>

#define K_CODES 8192
#define D_DIM   256
#define N_Q     16384
#define HW      1024
#define MQ      128          // queries per CTA
#define CCH     128          // codes per chunk
#define NCHUNKS (K_CODES / CCH)   // 64
#define WIN     2e-4f
#define MAXCAND 16

// ---------------- device scratch ----------------
__device__ __nv_bfloat16 g_ztb[(size_t)N_Q * D_DIM];   // z transposed, bf16
__device__ float g_ztf[(size_t)N_Q * D_DIM];           // z transposed, fp32 (exact fixup)
__device__ __nv_bfloat16 g_cbb[(size_t)K_CODES * D_DIM]; // codebook bf16
__device__ float g_c2[K_CODES];
__device__ float g_z2[N_Q];
__device__ int   g_ncand[N_Q];
__device__ int   g_cand[N_Q][MAXCAND];
__device__ int   g_idx[N_Q];

// ---------------- asm helpers ----------------
__device__ __forceinline__ uint32_t sm_u32(const void* p) {
    uint32_t a;
    asm("{ .reg .u64 t; cvta.to.shared.u64 t, %1; cvt.u32.u64 %0, t; }" : "=r"(a) : "l"(p));
    return a;
}
#define CP_ASYNC16(dst, src) \
    asm volatile("cp.async.cg.shared.global [%0], [%1], 16;" :: "r"(dst), "l"(src))
#define CP_COMMIT() asm volatile("cp.async.commit_group;" ::: "memory")
#define CP_WAIT(n)  asm volatile("cp.async.wait_group %0;" :: "n"(n) : "memory")

__device__ __forceinline__ void ldsm_x4(uint32_t& r0, uint32_t& r1, uint32_t& r2,
                                        uint32_t& r3, uint32_t addr) {
    asm volatile("ldmatrix.sync.aligned.m8n8.x4.shared.b16 {%0,%1,%2,%3}, [%4];"
                 : "=r"(r0), "=r"(r1), "=r"(r2), "=r"(r3) : "r"(addr));
}
// NON-trans: B rows are n-major with contiguous k -> plain ldmatrix gives the
// (n=T/4, k=2(T%4)+{0,1}) pairing the row.col B fragment requires. (proven R6)
__device__ __forceinline__ void ldsm_x2(uint32_t& r0, uint32_t& r1, uint32_t addr) {
    asm volatile("ldmatrix.sync.aligned.m8n8.x2.shared.b16 {%0,%1}, [%2];"
                 : "=r"(r0), "=r"(r1) : "r"(addr));
}
__device__ __forceinline__ void mma_bf16(float& d0, float& d1, float& d2, float& d3,
                                         uint32_t a0, uint32_t a1, uint32_t a2, uint32_t a3,
                                         uint32_t b0, uint32_t b1) {
    asm volatile("mma.sync.aligned.m16n8k16.row.col.f32.bf16.bf16.f32 "
                 "{%0,%1,%2,%3},{%4,%5,%6,%7},{%8,%9},{%0,%1,%2,%3};"
                 : "+f"(d0), "+f"(d1), "+f"(d2), "+f"(d3)
                 : "r"(a0), "r"(a1), "r"(a2), "r"(a3), "r"(b0), "r"(b1));
}
// swizzled byte offset within a [row][256 bf16] tile (512B rows, 16B units)
__device__ __forceinline__ uint32_t swz(uint32_t r, uint32_t u) {
    return r * 512u + ((u ^ (r & 7u)) << 4);
}

// ---------------- prep kernels ----------------
__global__ void k_prep_cb(const float* __restrict__ cb) {
    int i = blockIdx.x * blockDim.x + threadIdx.x;  // per float4
    float4 v = ((const float4*)cb)[i];
    ((__nv_bfloat162*)g_cbb)[i * 2] =
        __nv_bfloat162(__float2bfloat16(v.x), __float2bfloat16(v.y));
    ((__nv_bfloat162*)g_cbb)[i * 2 + 1] =
        __nv_bfloat162(__float2bfloat16(v.z), __float2bfloat16(v.w));
}

// exact c2 (proven round-1, verbatim)
__global__ void k_c2(const float* __restrict__ cb) {
    int w = (blockIdx.x * blockDim.x + threadIdx.x) >> 5;
    int lane = threadIdx.x & 31;
    if (w >= K_CODES) return;
    float s = 0.f;
#pragma unroll
    for (int i = 0; i < 8; i++) {
        float v = cb[(size_t)w * D_DIM + lane + i * 32];
        s = __fadd_rn(s, __fmul_rn(v, v));
    }
#pragma unroll
    for (int o = 16; o; o >>= 1) s = __fadd_rn(s, __shfl_xor_sync(0xffffffffu, s, o));
    if (lane == 0) g_c2[w] = s;
}

// exact z2 (proven round-1, verbatim)
__global__ void k_z2(const float* __restrict__ z) {
    int q = blockIdx.x * blockDim.x + threadIdx.x;
    int b = q >> 10, hw = q & 1023;
    const float* p = z + (size_t)b * (D_DIM * HW) + hw;
    float s = 0.f;
    for (int d = 0; d < D_DIM; d++) {
        float v = p[(size_t)d * HW];
        s = __fadd_rn(s, __fmul_rn(v, v));
    }
    g_z2[q] = s;
}

// NCHW -> [q][d] fp32 + bf16
__global__ void k_prep_z(const float* __restrict__ z) {
    __shared__ float tile[32][33];
    int b = blockIdx.z, d0 = blockIdx.y * 32, h0 = blockIdx.x * 32;
    int tx = threadIdx.x, ty = threadIdx.y;  // 32 x 8
#pragma unroll
    for (int j = 0; j < 32; j += 8)
        tile[ty + j][tx] = z[(size_t)(b * D_DIM + d0 + ty + j) * HW + h0 + tx];
    __syncthreads();
#pragma unroll
    for (int j = 0; j < 32; j += 8) {
        int q = b * HW + h0 + ty + j, d = d0 + tx;
        float vv = tile[tx][ty + j];
        g_ztf[(size_t)q * D_DIM + d] = vv;
        g_ztb[(size_t)q * D_DIM + d] = __float2bfloat16(vv);
    }
}

// ---------------- main HMMA kernel ----------------
// 512 threads, 16 warps: mw = w>>2 (32 query rows), nw = w&3 (32 codes)
// smem: A 64KB | B0 64KB | B1 64KB  (+1KB align pad)
__global__ __launch_bounds__(512, 1) void k_mma() {
    extern __shared__ char sraw[];
    uint32_t raw32 = sm_u32(sraw);
    uint32_t pad = (1024u - (raw32 & 1023u)) & 1023u;
    char* base = sraw + pad;
    const uint32_t sA = raw32 + pad;
    const uint32_t sB0 = sA + 65536u, sB1 = sB0 + 65536u;

    const int t = threadIdx.x, lane = t & 31, w = t >> 5;
    const int mw = w >> 2;          // 0..3 : query quarter (32 rows)
    const int nw = w & 3;           // 0..3 : code quarter within chunk (32 cols)
    const int q0 = blockIdx.x * MQ;

    // issue B chunk 0
    {
        const char* src = (const char*)(g_cbb);
#pragma unroll
        for (int i = 0; i < 8; i++) {
            int idx = i * 512 + t;
            uint32_t r = (uint32_t)(idx >> 5), u = (uint32_t)(idx & 31);
            CP_ASYNC16(sB0 + swz(r, u), src + (size_t)idx * 16);
        }
        CP_COMMIT();
    }
    // load A tile (128 q x 256 d bf16, swizzled)
    {
        const int4* src = (const int4*)(g_ztb + (size_t)q0 * D_DIM);
#pragma unroll
        for (int i = 0; i < 8; i++) {
            int idx = i * 512 + t;
            uint32_t r = (uint32_t)(idx >> 5), u = (uint32_t)(idx & 31);
            *(int4*)(base + swz(r, u)) = src[idx];
        }
    }

    // per-thread top-3 per row-slot (4 slots: mi*2 + half)
    float v1[4], v2[4], v3[4];
    int   k1[4], k2[4], k3[4];
#pragma unroll
    for (int i = 0; i < 4; i++) {
        v1[i] = __int_as_float(0x7f800000); v2[i] = v1[i]; v3[i] = v1[i];
        k1[i] = 0x7fffffff; k2[i] = k1[i]; k3[i] = k1[i];
    }

    // precompute A row bases (per mi), row fixed across k-iters
    uint32_t aRow[2], aR7[2];
#pragma unroll
    for (int mi = 0; mi < 2; mi++) {
        uint32_t r = (uint32_t)(mw * 32 + mi * 16 + (lane & 15));
        aRow[mi] = sA + r * 512u;
        aR7[mi] = r & 7u;
    }
    const uint32_t aU = (uint32_t)(lane >> 4);          // +0 or +1 16B unit (k 8-15)
    const uint32_t bRl = (uint32_t)(nw * 32 + (lane & 7));  // code row base (per ni add ni*8)
    const uint32_t bU = (uint32_t)((lane >> 3) & 1);    // lanes 8-15: k-unit +1 (b1 = k+8)

    for (int ch = 0; ch < NCHUNKS; ch++) {
        // issue next chunk, then wait for current
        if (ch + 1 < NCHUNKS) {
            uint32_t dstB = ((ch + 1) & 1) ? sB1 : sB0;
            const char* src = (const char*)(g_cbb + (size_t)(ch + 1) * CCH * D_DIM);
#pragma unroll
            for (int i = 0; i < 8; i++) {
                int idx = i * 512 + t;
                uint32_t r = (uint32_t)(idx >> 5), u = (uint32_t)(idx & 31);
                CP_ASYNC16(dstB + swz(r, u), src + (size_t)idx * 16);
            }
            CP_COMMIT();
            CP_WAIT(1);
        } else {
            CP_WAIT(0);
        }
        __syncthreads();

        const uint32_t sB = (ch & 1) ? sB1 : sB0;
        float acc[2][4][4];
#pragma unroll
        for (int mi = 0; mi < 2; mi++)
#pragma unroll
            for (int ni = 0; ni < 4; ni++)
#pragma unroll
                for (int e = 0; e < 4; e++) acc[mi][ni][e] = 0.f;

#pragma unroll
        for (int kk = 0; kk < 16; kk++) {
            uint32_t au = (uint32_t)(kk * 2) + aU;
            uint32_t af[2][4];
#pragma unroll
            for (int mi = 0; mi < 2; mi++)
                ldsm_x4(af[mi][0], af[mi][1], af[mi][2], af[mi][3],
                        aRow[mi] + ((au ^ aR7[mi]) << 4));
            uint32_t bu = (uint32_t)(kk * 2) + bU;
            uint32_t bf[4][2];
#pragma unroll
            for (int ni = 0; ni < 4; ni++) {
                uint32_t r = bRl + (uint32_t)(ni * 8);
                ldsm_x2(bf[ni][0], bf[ni][1], sB + r * 512u + ((bu ^ (r & 7u)) << 4));
            }
#pragma unroll
            for (int mi = 0; mi < 2; mi++)
#pragma unroll
                for (int ni = 0; ni < 4; ni++)
                    mma_bf16(acc[mi][ni][0], acc[mi][ni][1], acc[mi][ni][2], acc[mi][ni][3],
                             af[mi][0], af[mi][1], af[mi][2], af[mi][3],
                             bf[ni][0], bf[ni][1]);
        }

        // epilogue: s = c2 - 2*dot, fold into per-slot top-3 (codes ascending)
        const int kb = ch * CCH + nw * 32 + (lane & 3) * 2;
#pragma unroll
        for (int ni = 0; ni < 4; ni++) {
            float2 c2v = *(const float2*)(g_c2 + kb + ni * 8);
            int c0 = kb + ni * 8, c1 = c0 + 1;
#pragma unroll
            for (int mi = 0; mi < 2; mi++) {
#pragma unroll
                for (int half = 0; half < 2; half++) {
                    int sl = mi * 2 + half;
                    float s0 = __fmaf_rn(-2.f, acc[mi][ni][half * 2], c2v.x);
                    float s1 = __fmaf_rn(-2.f, acc[mi][ni][half * 2 + 1], c2v.y);
                    if (s0 < v3[sl]) {
                        if (s0 < v1[sl]) { v3[sl]=v2[sl];k3[sl]=k2[sl]; v2[sl]=v1[sl];k2[sl]=k1[sl]; v1[sl]=s0;k1[sl]=c0; }
                        else if (s0 < v2[sl]) { v3[sl]=v2[sl];k3[sl]=k2[sl]; v2[sl]=s0;k2[sl]=c0; }
                        else { v3[sl]=s0;k3[sl]=c0; }
                    }
                    if (s1 < v3[sl]) {
                        if (s1 < v1[sl]) { v3[sl]=v2[sl];k3[sl]=k2[sl]; v2[sl]=v1[sl];k2[sl]=k1[sl]; v1[sl]=s1;k1[sl]=c1; }
                        else if (s1 < v2[sl]) { v3[sl]=v2[sl];k3[sl]=k2[sl]; v2[sl]=s1;k2[sl]=c1; }
                        else { v3[sl]=s1;k3[sl]=c1; }
                    }
                }
            }
        }
        __syncthreads();
    }

    // ---- merge candidates: cand[q_local][48] in B0 region (48*8*128 = 49KB) ----
    float2* cand = (float2*)(base + 65536);
#pragma unroll
    for (int sl = 0; sl < 4; sl++) {
        int ql = mw * 32 + (sl >> 1) * 16 + (sl & 1) * 8 + (lane >> 2);
        int e = nw * 12 + (lane & 3) * 3;
        cand[ql * 48 + e]     = make_float2(v1[sl], __int_as_float(k1[sl]));
        cand[ql * 48 + e + 1] = make_float2(v2[sl], __int_as_float(k2[sl]));
        cand[ql * 48 + e + 2] = make_float2(v3[sl], __int_as_float(k3[sl]));
    }
    __syncthreads();
    if (t < MQ) {
        float m1 = __int_as_float(0x7f800000);
#pragma unroll
        for (int e = 0; e < 48; e++) m1 = fminf(m1, cand[t * 48 + e].x);
        float lim = m1 + WIN;
        // overflow only if some slot's 3rd-best is in window (a 4th could be hidden)
        int overflow = 0;
#pragma unroll
        for (int e = 2; e < 48; e += 3) overflow |= (cand[t * 48 + e].x <= lim);
        int q = q0 + t;
        int n = 0;
        if (!overflow) {
#pragma unroll
            for (int e = 0; e < 48; e++) {
                if ((e % 3) == 2) continue;  // v3 not in window (checked above)
                float2 c = cand[t * 48 + e];
                if (c.x <= lim && n < MAXCAND) g_cand[q][n++] = __float_as_int(c.y);
                else if (c.x <= lim) overflow = 1;  // cap exceeded -> safe fallback
            }
        }
        g_ncand[q] = overflow ? -1 : n;
    }
}

// ---------------- exact fixup ----------------
__device__ __forceinline__ float exact_dist(int q, int k, const float* __restrict__ cb) {
    const float* zr = g_ztf + (size_t)q * D_DIM;
    const float* cr = cb + (size_t)k * D_DIM;
    float acc = 0.f;
#pragma unroll 8
    for (int d = 0; d < D_DIM; d++) acc = __fmaf_rn(zr[d], cr[d], acc);
    return __fadd_rn(__fsub_rn(g_z2[q], __fmul_rn(2.0f, acc)), g_c2[k]);
}

__global__ void k_fixup(const float* __restrict__ cb) {
    int q = (blockIdx.x * blockDim.x + threadIdx.x) >> 5;
    int lane = threadIdx.x & 31;
    if (q >= N_Q) return;
    int n = g_ncand[q];
    float bv = __int_as_float(0x7f800000); int bk = 0x7fffffff;
    if (n < 0) {
        // safety net: exact full rescan (statistically unreachable now)
        for (int k = lane; k < K_CODES; k += 32) {
            float d = exact_dist(q, k, cb);
            if (d < bv || (d == bv && k < bk)) { bv = d; bk = k; }
        }
    } else if (lane < n) {
        bk = g_cand[q][lane];
        bv = exact_dist(q, bk, cb);
    }
#pragma unroll
    for (int o = 16; o; o >>= 1) {
        float ov = __shfl_xor_sync(0xffffffffu, bv, o);
        int   ok = __shfl_xor_sync(0xffffffffu, bk, o);
        if (ov < bv || (ov == bv && ok < bk)) { bv = ov; bk = ok; }
    }
    if (lane == 0) g_idx[q] = bk;
}

// ---------------- z_q writer (exact straight-through arithmetic) ----------------
__global__ __launch_bounds__(256) void k_zq(const float* __restrict__ z,
                                            const float* __restrict__ cb,
                                            float* __restrict__ out, int write_idx) {
    __shared__ int sidx[MQ];
    int t = threadIdx.x, qb = blockIdx.x * MQ;
    int b = qb >> 10, hw0 = qb & 1023;
    if (t < MQ) {
        int ix = g_idx[qb + t];
        sidx[t] = ix;
        if (write_idx) out[(size_t)N_Q * D_DIM + qb + t] = (float)ix;
    }
    __syncthreads();
#pragma unroll 4
    for (int i = 0; i < 128; i++) {
        int idx2 = t + i * 256;
        int d = idx2 >> 7, q = idx2 & 127;
        float zv = z[(size_t)b * (D_DIM * HW) + (size_t)d * HW + hw0 + q];
        float cv = cb[(size_t)sidx[q] * D_DIM + d];
        out[(size_t)b * (D_DIM * HW) + (size_t)d * HW + hw0 + q] =
            __fadd_rn(zv, __fsub_rn(cv, zv));
    }
}

// ---------------- launch ----------------
extern "C" void kernel_launch(void* const* d_in, const int* in_sizes, int n_in,
                              void* d_out, int out_size) {
    const float* z_e = (const float*)d_in[0];
    const float* cb  = (const float*)d_in[1];
    float* out = (float*)d_out;

    const size_t smem = 3 * 65536 + 1024;  // A + 2 B stages + align pad = 197632
    cudaFuncSetAttribute(k_mma, cudaFuncAttributeMaxDynamicSharedMemorySize, (int)smem);
    int write_idx = (out_size >= (int)(N_Q * D_DIM + N_Q)) ? 1 : 0;

    // k_mma deliberately placed as the 4th launch: ncu captures launch #4,
    // and z2 is only consumed by k_fixup (safe to run after k_mma).
    k_prep_cb<<<(K_CODES * D_DIM / 4) / 256, 256>>>(cb);
    k_c2<<<(K_CODES * 32) / 256, 256>>>(cb);
    k_prep_z<<<dim3(HW / 32, D_DIM / 32, 16), dim3(32, 8)>>>(z_e);
    k_mma<<<N_Q / MQ, 512, smem>>>();
    k_z2<<<N_Q / 256, 256>>>(z_e);
    k_fixup<<<(N_Q * 32) / 256, 256>>>(cb);
    k_zq<<<N_Q / MQ, 256>>>(z_e, cb, out, write_idx);
}

// round 12
// speedup vs baseline: 6.7954x; 1.0106x over previous
#include <cuda_runtime.h>
#include <cuda_bf16.h>
#include <cstdint>

#define K_CODES 8192
#define D_DIM   256
#define N_Q     16384
#define HW      1024
#define MQ      128          // queries per CTA
#define CCH     128          // codes per chunk
#define NCHUNKS (K_CODES / CCH)   // 64
#define WIN     2e-4f
#define MAXCAND 16

// ---------------- device scratch ----------------
__device__ __nv_bfloat16 g_ztb[(size_t)N_Q * D_DIM];   // z transposed, bf16
__device__ float g_ztf[(size_t)N_Q * D_DIM];           // z transposed, fp32 (exact fixup)
__device__ __nv_bfloat16 g_cbb[(size_t)K_CODES * D_DIM]; // codebook bf16
__device__ float g_cbT[(size_t)D_DIM * K_CODES];       // codebook fp32 transposed [d][k]
__device__ float g_c2[K_CODES];
__device__ float g_z2[N_Q];
__device__ int   g_ncand[N_Q];
__device__ int   g_cand[N_Q][MAXCAND];
__device__ int   g_idx[N_Q];

// ---------------- asm helpers ----------------
__device__ __forceinline__ uint32_t sm_u32(const void* p) {
    uint32_t a;
    asm("{ .reg .u64 t; cvta.to.shared.u64 t, %1; cvt.u32.u64 %0, t; }" : "=r"(a) : "l"(p));
    return a;
}
#define CP_ASYNC16(dst, src) \
    asm volatile("cp.async.cg.shared.global [%0], [%1], 16;" :: "r"(dst), "l"(src))
#define CP_COMMIT() asm volatile("cp.async.commit_group;" ::: "memory")
#define CP_WAIT(n)  asm volatile("cp.async.wait_group %0;" :: "n"(n) : "memory")

__device__ __forceinline__ void ldsm_x4(uint32_t& r0, uint32_t& r1, uint32_t& r2,
                                        uint32_t& r3, uint32_t addr) {
    asm volatile("ldmatrix.sync.aligned.m8n8.x4.shared.b16 {%0,%1,%2,%3}, [%4];"
                 : "=r"(r0), "=r"(r1), "=r"(r2), "=r"(r3) : "r"(addr));
}
// NON-trans ldmatrix for B (proven round 6)
__device__ __forceinline__ void ldsm_x2(uint32_t& r0, uint32_t& r1, uint32_t addr) {
    asm volatile("ldmatrix.sync.aligned.m8n8.x2.shared.b16 {%0,%1}, [%2];"
                 : "=r"(r0), "=r"(r1) : "r"(addr));
}
__device__ __forceinline__ void mma_bf16(float& d0, float& d1, float& d2, float& d3,
                                         uint32_t a0, uint32_t a1, uint32_t a2, uint32_t a3,
                                         uint32_t b0, uint32_t b1) {
    asm volatile("mma.sync.aligned.m16n8k16.row.col.f32.bf16.bf16.f32 "
                 "{%0,%1,%2,%3},{%4,%5,%6,%7},{%8,%9},{%0,%1,%2,%3};"
                 : "+f"(d0), "+f"(d1), "+f"(d2), "+f"(d3)
                 : "r"(a0), "r"(a1), "r"(a2), "r"(a3), "r"(b0), "r"(b1));
}
__device__ __forceinline__ uint32_t swz(uint32_t r, uint32_t u) {
    return r * 512u + ((u ^ (r & 7u)) << 4);
}

// ---------------- kernel 1: codebook prep (bf16 split + fp32 transpose + exact c2) ----------------
// grid: [0,2048) bf16 convert, [2048,4096) transpose, [4096,5120) c2
__global__ void k_prep_code(const float* __restrict__ cb) {
    int bx = blockIdx.x, t = threadIdx.x;
    if (bx < 2048) {
        int i = bx * 256 + t;  // per float4
        float4 v = ((const float4*)cb)[i];
        ((__nv_bfloat162*)g_cbb)[i * 2] =
            __nv_bfloat162(__float2bfloat16(v.x), __float2bfloat16(v.y));
        ((__nv_bfloat162*)g_cbb)[i * 2 + 1] =
            __nv_bfloat162(__float2bfloat16(v.z), __float2bfloat16(v.w));
    } else if (bx < 4096) {
        // transpose cb[k][d] -> g_cbT[d][k] (proven round-1 tile pattern)
        __shared__ float tile[32][33];
        int bb = bx - 2048;
        int k0 = (bb & 255) * 32, d0 = (bb >> 8) * 32;
        int tx = t & 31, ty = t >> 5;  // 32 x 8
#pragma unroll
        for (int j = 0; j < 32; j += 8)
            tile[ty + j][tx] = cb[(size_t)(k0 + ty + j) * D_DIM + d0 + tx];
        __syncthreads();
#pragma unroll
        for (int j = 0; j < 32; j += 8)
            g_cbT[(size_t)(d0 + ty + j) * K_CODES + k0 + tx] = tile[tx][ty + j];
    } else {
        // exact c2 (proven round-1 pattern, verbatim arithmetic)
        int w = ((bx - 4096) * 256 + t) >> 5;
        int lane = t & 31;
        if (w >= K_CODES) return;
        float s = 0.f;
#pragma unroll
        for (int i = 0; i < 8; i++) {
            float v = cb[(size_t)w * D_DIM + lane + i * 32];
            s = __fadd_rn(s, __fmul_rn(v, v));
        }
#pragma unroll
        for (int o = 16; o; o >>= 1) s = __fadd_rn(s, __shfl_xor_sync(0xffffffffu, s, o));
        if (lane == 0) g_c2[w] = s;
    }
}

// ---------------- kernel 2: z prep (NCHW->[q][d] fp32+bf16) + exact z2 ----------------
// grid: [0,4096) transpose, [4096,4160) z2
__global__ void k_prep_z(const float* __restrict__ z) {
    int bx = blockIdx.x, t = threadIdx.x;
    if (bx < 4096) {
        __shared__ float tile[32][33];
        int h0 = (bx & 31) * 32, d0 = ((bx >> 5) & 7) * 32, b = bx >> 8;
        int tx = t & 31, ty = t >> 5;  // 32 x 8
#pragma unroll
        for (int j = 0; j < 32; j += 8)
            tile[ty + j][tx] = z[(size_t)(b * D_DIM + d0 + ty + j) * HW + h0 + tx];
        __syncthreads();
#pragma unroll
        for (int j = 0; j < 32; j += 8) {
            int q = b * HW + h0 + ty + j, d = d0 + tx;
            float vv = tile[tx][ty + j];
            g_ztf[(size_t)q * D_DIM + d] = vv;
            g_ztb[(size_t)q * D_DIM + d] = __float2bfloat16(vv);
        }
    } else {
        // exact z2 (proven round-1, verbatim arithmetic)
        int q = (bx - 4096) * 256 + t;
        int b = q >> 10, hw = q & 1023;
        const float* p = z + (size_t)b * (D_DIM * HW) + hw;
        float s = 0.f;
        for (int d = 0; d < D_DIM; d++) {
            float v = p[(size_t)d * HW];
            s = __fadd_rn(s, __fmul_rn(v, v));
        }
        g_z2[q] = s;
    }
}

// ---------------- kernel 3: main HMMA (unchanged from round 10: 278us measured) ----------------
__global__ __launch_bounds__(512, 1) void k_mma() {
    extern __shared__ char sraw[];
    uint32_t raw32 = sm_u32(sraw);
    uint32_t pad = (1024u - (raw32 & 1023u)) & 1023u;
    char* base = sraw + pad;
    const uint32_t sA = raw32 + pad;
    const uint32_t sB0 = sA + 65536u, sB1 = sB0 + 65536u;

    const int t = threadIdx.x, lane = t & 31, w = t >> 5;
    const int mw = w >> 2;
    const int nw = w & 3;
    const int q0 = blockIdx.x * MQ;

    {
        const char* src = (const char*)(g_cbb);
#pragma unroll
        for (int i = 0; i < 8; i++) {
            int idx = i * 512 + t;
            uint32_t r = (uint32_t)(idx >> 5), u = (uint32_t)(idx & 31);
            CP_ASYNC16(sB0 + swz(r, u), src + (size_t)idx * 16);
        }
        CP_COMMIT();
    }
    {
        const int4* src = (const int4*)(g_ztb + (size_t)q0 * D_DIM);
#pragma unroll
        for (int i = 0; i < 8; i++) {
            int idx = i * 512 + t;
            uint32_t r = (uint32_t)(idx >> 5), u = (uint32_t)(idx & 31);
            *(int4*)(base + swz(r, u)) = src[idx];
        }
    }

    float v1[4], v2[4], v3[4];
    int   k1[4], k2[4], k3[4];
#pragma unroll
    for (int i = 0; i < 4; i++) {
        v1[i] = __int_as_float(0x7f800000); v2[i] = v1[i]; v3[i] = v1[i];
        k1[i] = 0x7fffffff; k2[i] = k1[i]; k3[i] = k1[i];
    }

    uint32_t aRow[2], aR7[2];
#pragma unroll
    for (int mi = 0; mi < 2; mi++) {
        uint32_t r = (uint32_t)(mw * 32 + mi * 16 + (lane & 15));
        aRow[mi] = sA + r * 512u;
        aR7[mi] = r & 7u;
    }
    const uint32_t aU = (uint32_t)(lane >> 4);
    const uint32_t bRl = (uint32_t)(nw * 32 + (lane & 7));
    const uint32_t bU = (uint32_t)((lane >> 3) & 1);

    for (int ch = 0; ch < NCHUNKS; ch++) {
        if (ch + 1 < NCHUNKS) {
            uint32_t dstB = ((ch + 1) & 1) ? sB1 : sB0;
            const char* src = (const char*)(g_cbb + (size_t)(ch + 1) * CCH * D_DIM);
#pragma unroll
            for (int i = 0; i < 8; i++) {
                int idx = i * 512 + t;
                uint32_t r = (uint32_t)(idx >> 5), u = (uint32_t)(idx & 31);
                CP_ASYNC16(dstB + swz(r, u), src + (size_t)idx * 16);
            }
            CP_COMMIT();
            CP_WAIT(1);
        } else {
            CP_WAIT(0);
        }
        __syncthreads();

        const uint32_t sB = (ch & 1) ? sB1 : sB0;
        float acc[2][4][4];
#pragma unroll
        for (int mi = 0; mi < 2; mi++)
#pragma unroll
            for (int ni = 0; ni < 4; ni++)
#pragma unroll
                for (int e = 0; e < 4; e++) acc[mi][ni][e] = 0.f;

#pragma unroll
        for (int kk = 0; kk < 16; kk++) {
            uint32_t au = (uint32_t)(kk * 2) + aU;
            uint32_t af[2][4];
#pragma unroll
            for (int mi = 0; mi < 2; mi++)
                ldsm_x4(af[mi][0], af[mi][1], af[mi][2], af[mi][3],
                        aRow[mi] + ((au ^ aR7[mi]) << 4));
            uint32_t bu = (uint32_t)(kk * 2) + bU;
            uint32_t bf[4][2];
#pragma unroll
            for (int ni = 0; ni < 4; ni++) {
                uint32_t r = bRl + (uint32_t)(ni * 8);
                ldsm_x2(bf[ni][0], bf[ni][1], sB + r * 512u + ((bu ^ (r & 7u)) << 4));
            }
#pragma unroll
            for (int mi = 0; mi < 2; mi++)
#pragma unroll
                for (int ni = 0; ni < 4; ni++)
                    mma_bf16(acc[mi][ni][0], acc[mi][ni][1], acc[mi][ni][2], acc[mi][ni][3],
                             af[mi][0], af[mi][1], af[mi][2], af[mi][3],
                             bf[ni][0], bf[ni][1]);
        }

        const int kb = ch * CCH + nw * 32 + (lane & 3) * 2;
#pragma unroll
        for (int ni = 0; ni < 4; ni++) {
            float2 c2v = *(const float2*)(g_c2 + kb + ni * 8);
            int c0 = kb + ni * 8, c1 = c0 + 1;
#pragma unroll
            for (int mi = 0; mi < 2; mi++) {
#pragma unroll
                for (int half = 0; half < 2; half++) {
                    int sl = mi * 2 + half;
                    float s0 = __fmaf_rn(-2.f, acc[mi][ni][half * 2], c2v.x);
                    float s1 = __fmaf_rn(-2.f, acc[mi][ni][half * 2 + 1], c2v.y);
                    if (s0 < v3[sl]) {
                        if (s0 < v1[sl]) { v3[sl]=v2[sl];k3[sl]=k2[sl]; v2[sl]=v1[sl];k2[sl]=k1[sl]; v1[sl]=s0;k1[sl]=c0; }
                        else if (s0 < v2[sl]) { v3[sl]=v2[sl];k3[sl]=k2[sl]; v2[sl]=s0;k2[sl]=c0; }
                        else { v3[sl]=s0;k3[sl]=c0; }
                    }
                    if (s1 < v3[sl]) {
                        if (s1 < v1[sl]) { v3[sl]=v2[sl];k3[sl]=k2[sl]; v2[sl]=v1[sl];k2[sl]=k1[sl]; v1[sl]=s1;k1[sl]=c1; }
                        else if (s1 < v2[sl]) { v3[sl]=v2[sl];k3[sl]=k2[sl]; v2[sl]=s1;k2[sl]=c1; }
                        else { v3[sl]=s1;k3[sl]=c1; }
                    }
                }
            }
        }
        __syncthreads();
    }

    float2* cand = (float2*)(base + 65536);
#pragma unroll
    for (int sl = 0; sl < 4; sl++) {
        int ql = mw * 32 + (sl >> 1) * 16 + (sl & 1) * 8 + (lane >> 2);
        int e = nw * 12 + (lane & 3) * 3;
        cand[ql * 48 + e]     = make_float2(v1[sl], __int_as_float(k1[sl]));
        cand[ql * 48 + e + 1] = make_float2(v2[sl], __int_as_float(k2[sl]));
        cand[ql * 48 + e + 2] = make_float2(v3[sl], __int_as_float(k3[sl]));
    }
    __syncthreads();
    if (t < MQ) {
        float m1 = __int_as_float(0x7f800000);
#pragma unroll
        for (int e = 0; e < 48; e++) m1 = fminf(m1, cand[t * 48 + e].x);
        float lim = m1 + WIN;
        int overflow = 0;
#pragma unroll
        for (int e = 2; e < 48; e += 3) overflow |= (cand[t * 48 + e].x <= lim);
        int q = q0 + t;
        int n = 0;
        if (!overflow) {
#pragma unroll
            for (int e = 0; e < 48; e++) {
                if ((e % 3) == 2) continue;
                float2 c = cand[t * 48 + e];
                if (c.x <= lim && n < MAXCAND) g_cand[q][n++] = __float_as_int(c.y);
                else if (c.x <= lim) overflow = 1;
            }
        }
        g_ncand[q] = overflow ? -1 : n;
    }
}

// ---------------- kernel 4: exact fixup (coalesced via transposed codebook) ----------------
// exact chain preserved: sequential d=0..255 fused FMA per code, fl(fl(z2-2dot)+c2)
__global__ void k_fixup() {
    int q = (blockIdx.x * blockDim.x + threadIdx.x) >> 5;
    int lane = threadIdx.x & 31;
    if (q >= N_Q) return;
    int n = g_ncand[q];
    const float* zr = g_ztf + (size_t)q * D_DIM;
    float z2v = g_z2[q];
    float bv = __int_as_float(0x7f800000); int bk = 0x7fffffff;
    if (n < 0) {
        // full rescan, coalesced: lane k strides 32; 4 independent exact chains for ILP
        for (int i = 0; i < 256; i += 4) {
            int ka = lane + i * 32, kb = ka + 32, kc = ka + 64, kd = ka + 96;
            float a0 = 0.f, a1 = 0.f, a2 = 0.f, a3 = 0.f;
            for (int d = 0; d < D_DIM; d++) {
                float zv = zr[d];
                const float* row = g_cbT + (size_t)d * K_CODES;
                a0 = __fmaf_rn(zv, row[ka], a0);
                a1 = __fmaf_rn(zv, row[kb], a1);
                a2 = __fmaf_rn(zv, row[kc], a2);
                a3 = __fmaf_rn(zv, row[kd], a3);
            }
            float d0 = __fadd_rn(__fsub_rn(z2v, __fmul_rn(2.0f, a0)), g_c2[ka]);
            float d1 = __fadd_rn(__fsub_rn(z2v, __fmul_rn(2.0f, a1)), g_c2[kb]);
            float d2 = __fadd_rn(__fsub_rn(z2v, __fmul_rn(2.0f, a2)), g_c2[kc]);
            float d3 = __fadd_rn(__fsub_rn(z2v, __fmul_rn(2.0f, a3)), g_c2[kd]);
            if (d0 < bv || (d0 == bv && ka < bk)) { bv = d0; bk = ka; }
            if (d1 < bv || (d1 == bv && kb < bk)) { bv = d1; bk = kb; }
            if (d2 < bv || (d2 == bv && kc < bk)) { bv = d2; bk = kc; }
            if (d3 < bv || (d3 == bv && kd < bk)) { bv = d3; bk = kd; }
        }
    } else if (lane < n) {
        int k = g_cand[q][lane];
        float acc = 0.f;
#pragma unroll 8
        for (int d = 0; d < D_DIM; d++)
            acc = __fmaf_rn(zr[d], g_cbT[(size_t)d * K_CODES + k], acc);
        bv = __fadd_rn(__fsub_rn(z2v, __fmul_rn(2.0f, acc)), g_c2[k]);
        bk = k;
    }
#pragma unroll
    for (int o = 16; o; o >>= 1) {
        float ov = __shfl_xor_sync(0xffffffffu, bv, o);
        int   ok = __shfl_xor_sync(0xffffffffu, bk, o);
        if (ov < bv || (ov == bv && ok < bk)) { bv = ov; bk = ok; }
    }
    if (lane == 0) g_idx[q] = bk;
}

// ---------------- kernel 5: z_q writer (exact straight-through arithmetic) ----------------
__global__ __launch_bounds__(256) void k_zq(const float* __restrict__ z,
                                            const float* __restrict__ cb,
                                            float* __restrict__ out, int write_idx) {
    __shared__ int sidx[MQ];
    int t = threadIdx.x, qb = blockIdx.x * MQ;
    int b = qb >> 10, hw0 = qb & 1023;
    if (t < MQ) {
        int ix = g_idx[qb + t];
        sidx[t] = ix;
        if (write_idx) out[(size_t)N_Q * D_DIM + qb + t] = (float)ix;
    }
    __syncthreads();
#pragma unroll 4
    for (int i = 0; i < 128; i++) {
        int idx2 = t + i * 256;
        int d = idx2 >> 7, q = idx2 & 127;
        float zv = z[(size_t)b * (D_DIM * HW) + (size_t)d * HW + hw0 + q];
        float cv = cb[(size_t)sidx[q] * D_DIM + d];
        out[(size_t)b * (D_DIM * HW) + (size_t)d * HW + hw0 + q] =
            __fadd_rn(zv, __fsub_rn(cv, zv));
    }
}

// ---------------- launch ----------------
extern "C" void kernel_launch(void* const* d_in, const int* in_sizes, int n_in,
                              void* d_out, int out_size) {
    const float* z_e = (const float*)d_in[0];
    const float* cb  = (const float*)d_in[1];
    float* out = (float*)d_out;

    const size_t smem = 3 * 65536 + 1024;
    cudaFuncSetAttribute(k_mma, cudaFuncAttributeMaxDynamicSharedMemorySize, (int)smem);
    int write_idx = (out_size >= (int)(N_Q * D_DIM + N_Q)) ? 1 : 0;

    // launch order chosen so k_fixup is launch #4 (the slot ncu captures)
    k_prep_code<<<5120, 256>>>(cb);
    k_prep_z<<<4160, 256>>>(z_e);
    k_mma<<<N_Q / MQ, 512, smem>>>();
    k_fixup<<<(N_Q * 32) / 256, 256>>>();
    k_zq<<<N_Q / MQ, 256>>>(z_e, cb, out, write_idx);
}

// round 14
// speedup vs baseline: 8.9190x; 1.3125x over previous
#include <cuda_runtime.h>
#include <cuda_bf16.h>
#include <cstdint>

#define K_CODES 8192
#define D_DIM   256
#define N_Q     16384
#define HW      1024
#define MQ      128          // queries per CTA
#define CCH     128          // codes per chunk
#define NCHUNKS (K_CODES / CCH)   // 64
#define WIN     2e-4f
#define MAXCAND 16

// ---------------- device scratch ----------------
__device__ __nv_bfloat16 g_ztb[(size_t)N_Q * D_DIM];   // z transposed, bf16
__device__ float g_ztf[(size_t)N_Q * D_DIM];           // z transposed, fp32 (exact fixup)
__device__ __nv_bfloat16 g_cbb[(size_t)K_CODES * D_DIM]; // codebook bf16
__device__ float g_cbT[(size_t)D_DIM * K_CODES];       // codebook fp32 transposed [d][k]
__device__ float g_c2[K_CODES];
__device__ float g_z2[N_Q];
__device__ int   g_ncand[N_Q];
__device__ int   g_cand[N_Q][MAXCAND];

// ---------------- asm helpers ----------------
__device__ __forceinline__ uint32_t sm_u32(const void* p) {
    uint32_t a;
    asm("{ .reg .u64 t; cvta.to.shared.u64 t, %1; cvt.u32.u64 %0, t; }" : "=r"(a) : "l"(p));
    return a;
}
#define CP_ASYNC16(dst, src) \
    asm volatile("cp.async.cg.shared.global [%0], [%1], 16;" :: "r"(dst), "l"(src))
#define CP_COMMIT() asm volatile("cp.async.commit_group;" ::: "memory")
#define CP_WAIT(n)  asm volatile("cp.async.wait_group %0;" :: "n"(n) : "memory")

__device__ __forceinline__ void ldsm_x4(uint32_t& r0, uint32_t& r1, uint32_t& r2,
                                        uint32_t& r3, uint32_t addr) {
    asm volatile("ldmatrix.sync.aligned.m8n8.x4.shared.b16 {%0,%1,%2,%3}, [%4];"
                 : "=r"(r0), "=r"(r1), "=r"(r2), "=r"(r3) : "r"(addr));
}
// NON-trans ldmatrix for B (proven round 6)
__device__ __forceinline__ void ldsm_x2(uint32_t& r0, uint32_t& r1, uint32_t addr) {
    asm volatile("ldmatrix.sync.aligned.m8n8.x2.shared.b16 {%0,%1}, [%2];"
                 : "=r"(r0), "=r"(r1) : "r"(addr));
}
__device__ __forceinline__ void mma_bf16(float& d0, float& d1, float& d2, float& d3,
                                         uint32_t a0, uint32_t a1, uint32_t a2, uint32_t a3,
                                         uint32_t b0, uint32_t b1) {
    asm volatile("mma.sync.aligned.m16n8k16.row.col.f32.bf16.bf16.f32 "
                 "{%0,%1,%2,%3},{%4,%5,%6,%7},{%8,%9},{%0,%1,%2,%3};"
                 : "+f"(d0), "+f"(d1), "+f"(d2), "+f"(d3)
                 : "r"(a0), "r"(a1), "r"(a2), "r"(a3), "r"(b0), "r"(b1));
}
__device__ __forceinline__ uint32_t swz(uint32_t r, uint32_t u) {
    return r * 512u + ((u ^ (r & 7u)) << 4);
}

// ---------------- kernel 1: codebook prep (bf16 + fp32 transpose + exact c2) ----------------
__global__ void k_prep_code(const float* __restrict__ cb) {
    int bx = blockIdx.x, t = threadIdx.x;
    if (bx < 2048) {
        int i = bx * 256 + t;
        float4 v = ((const float4*)cb)[i];
        ((__nv_bfloat162*)g_cbb)[i * 2] =
            __nv_bfloat162(__float2bfloat16(v.x), __float2bfloat16(v.y));
        ((__nv_bfloat162*)g_cbb)[i * 2 + 1] =
            __nv_bfloat162(__float2bfloat16(v.z), __float2bfloat16(v.w));
    } else if (bx < 4096) {
        __shared__ float tile[32][33];
        int bb = bx - 2048;
        int k0 = (bb & 255) * 32, d0 = (bb >> 8) * 32;
        int tx = t & 31, ty = t >> 5;
#pragma unroll
        for (int j = 0; j < 32; j += 8)
            tile[ty + j][tx] = cb[(size_t)(k0 + ty + j) * D_DIM + d0 + tx];
        __syncthreads();
#pragma unroll
        for (int j = 0; j < 32; j += 8)
            g_cbT[(size_t)(d0 + ty + j) * K_CODES + k0 + tx] = tile[tx][ty + j];
    } else {
        // exact c2 (proven round-1 arithmetic)
        int w = ((bx - 4096) * 256 + t) >> 5;
        int lane = t & 31;
        if (w >= K_CODES) return;
        float s = 0.f;
#pragma unroll
        for (int i = 0; i < 8; i++) {
            float v = cb[(size_t)w * D_DIM + lane + i * 32];
            s = __fadd_rn(s, __fmul_rn(v, v));
        }
#pragma unroll
        for (int o = 16; o; o >>= 1) s = __fadd_rn(s, __shfl_xor_sync(0xffffffffu, s, o));
        if (lane == 0) g_c2[w] = s;
    }
}

// ---------------- kernel 2: z prep + exact z2 ----------------
__global__ void k_prep_z(const float* __restrict__ z) {
    int bx = blockIdx.x, t = threadIdx.x;
    if (bx < 4096) {
        __shared__ float tile[32][33];
        int h0 = (bx & 31) * 32, d0 = ((bx >> 5) & 7) * 32, b = bx >> 8;
        int tx = t & 31, ty = t >> 5;
#pragma unroll
        for (int j = 0; j < 32; j += 8)
            tile[ty + j][tx] = z[(size_t)(b * D_DIM + d0 + ty + j) * HW + h0 + tx];
        __syncthreads();
#pragma unroll
        for (int j = 0; j < 32; j += 8) {
            int q = b * HW + h0 + ty + j, d = d0 + tx;
            float vv = tile[tx][ty + j];
            g_ztf[(size_t)q * D_DIM + d] = vv;
            g_ztb[(size_t)q * D_DIM + d] = __float2bfloat16(vv);
        }
    } else {
        // exact z2 (proven round-1 arithmetic)
        int q = (bx - 4096) * 256 + t;
        int b = q >> 10, hw = q & 1023;
        const float* p = z + (size_t)b * (D_DIM * HW) + hw;
        float s = 0.f;
        for (int d = 0; d < D_DIM; d++) {
            float v = p[(size_t)d * HW];
            s = __fadd_rn(s, __fmul_rn(v, v));
        }
        g_z2[q] = s;
    }
}

// ---------------- kernel 3: main HMMA (unchanged; 278us measured R10) ----------------
__global__ __launch_bounds__(512, 1) void k_mma() {
    extern __shared__ char sraw[];
    uint32_t raw32 = sm_u32(sraw);
    uint32_t pad = (1024u - (raw32 & 1023u)) & 1023u;
    char* base = sraw + pad;
    const uint32_t sA = raw32 + pad;
    const uint32_t sB0 = sA + 65536u, sB1 = sB0 + 65536u;

    const int t = threadIdx.x, lane = t & 31, w = t >> 5;
    const int mw = w >> 2;
    const int nw = w & 3;
    const int q0 = blockIdx.x * MQ;

    {
        const char* src = (const char*)(g_cbb);
#pragma unroll
        for (int i = 0; i < 8; i++) {
            int idx = i * 512 + t;
            uint32_t r = (uint32_t)(idx >> 5), u = (uint32_t)(idx & 31);
            CP_ASYNC16(sB0 + swz(r, u), src + (size_t)idx * 16);
        }
        CP_COMMIT();
    }
    {
        const int4* src = (const int4*)(g_ztb + (size_t)q0 * D_DIM);
#pragma unroll
        for (int i = 0; i < 8; i++) {
            int idx = i * 512 + t;
            uint32_t r = (uint32_t)(idx >> 5), u = (uint32_t)(idx & 31);
            *(int4*)(base + swz(r, u)) = src[idx];
        }
    }

    float v1[4], v2[4], v3[4];
    int   k1[4], k2[4], k3[4];
#pragma unroll
    for (int i = 0; i < 4; i++) {
        v1[i] = __int_as_float(0x7f800000); v2[i] = v1[i]; v3[i] = v1[i];
        k1[i] = 0x7fffffff; k2[i] = k1[i]; k3[i] = k1[i];
    }

    uint32_t aRow[2], aR7[2];
#pragma unroll
    for (int mi = 0; mi < 2; mi++) {
        uint32_t r = (uint32_t)(mw * 32 + mi * 16 + (lane & 15));
        aRow[mi] = sA + r * 512u;
        aR7[mi] = r & 7u;
    }
    const uint32_t aU = (uint32_t)(lane >> 4);
    const uint32_t bRl = (uint32_t)(nw * 32 + (lane & 7));
    const uint32_t bU = (uint32_t)((lane >> 3) & 1);

    for (int ch = 0; ch < NCHUNKS; ch++) {
        if (ch + 1 < NCHUNKS) {
            uint32_t dstB = ((ch + 1) & 1) ? sB1 : sB0;
            const char* src = (const char*)(g_cbb + (size_t)(ch + 1) * CCH * D_DIM);
#pragma unroll
            for (int i = 0; i < 8; i++) {
                int idx = i * 512 + t;
                uint32_t r = (uint32_t)(idx >> 5), u = (uint32_t)(idx & 31);
                CP_ASYNC16(dstB + swz(r, u), src + (size_t)idx * 16);
            }
            CP_COMMIT();
            CP_WAIT(1);
        } else {
            CP_WAIT(0);
        }
        __syncthreads();

        const uint32_t sB = (ch & 1) ? sB1 : sB0;
        float acc[2][4][4];
#pragma unroll
        for (int mi = 0; mi < 2; mi++)
#pragma unroll
            for (int ni = 0; ni < 4; ni++)
#pragma unroll
                for (int e = 0; e < 4; e++) acc[mi][ni][e] = 0.f;

#pragma unroll
        for (int kk = 0; kk < 16; kk++) {
            uint32_t au = (uint32_t)(kk * 2) + aU;
            uint32_t af[2][4];
#pragma unroll
            for (int mi = 0; mi < 2; mi++)
                ldsm_x4(af[mi][0], af[mi][1], af[mi][2], af[mi][3],
                        aRow[mi] + ((au ^ aR7[mi]) << 4));
            uint32_t bu = (uint32_t)(kk * 2) + bU;
            uint32_t bf[4][2];
#pragma unroll
            for (int ni = 0; ni < 4; ni++) {
                uint32_t r = bRl + (uint32_t)(ni * 8);
                ldsm_x2(bf[ni][0], bf[ni][1], sB + r * 512u + ((bu ^ (r & 7u)) << 4));
            }
#pragma unroll
            for (int mi = 0; mi < 2; mi++)
#pragma unroll
                for (int ni = 0; ni < 4; ni++)
                    mma_bf16(acc[mi][ni][0], acc[mi][ni][1], acc[mi][ni][2], acc[mi][ni][3],
                             af[mi][0], af[mi][1], af[mi][2], af[mi][3],
                             bf[ni][0], bf[ni][1]);
        }

        const int kb = ch * CCH + nw * 32 + (lane & 3) * 2;
#pragma unroll
        for (int ni = 0; ni < 4; ni++) {
            float2 c2v = *(const float2*)(g_c2 + kb + ni * 8);
            int c0 = kb + ni * 8, c1 = c0 + 1;
#pragma unroll
            for (int mi = 0; mi < 2; mi++) {
#pragma unroll
                for (int half = 0; half < 2; half++) {
                    int sl = mi * 2 + half;
                    float s0 = __fmaf_rn(-2.f, acc[mi][ni][half * 2], c2v.x);
                    float s1 = __fmaf_rn(-2.f, acc[mi][ni][half * 2 + 1], c2v.y);
                    if (s0 < v3[sl]) {
                        if (s0 < v1[sl]) { v3[sl]=v2[sl];k3[sl]=k2[sl]; v2[sl]=v1[sl];k2[sl]=k1[sl]; v1[sl]=s0;k1[sl]=c0; }
                        else if (s0 < v2[sl]) { v3[sl]=v2[sl];k3[sl]=k2[sl]; v2[sl]=s0;k2[sl]=c0; }
                        else { v3[sl]=s0;k3[sl]=c0; }
                    }
                    if (s1 < v3[sl]) {
                        if (s1 < v1[sl]) { v3[sl]=v2[sl];k3[sl]=k2[sl]; v2[sl]=v1[sl];k2[sl]=k1[sl]; v1[sl]=s1;k1[sl]=c1; }
                        else if (s1 < v2[sl]) { v3[sl]=v2[sl];k3[sl]=k2[sl]; v2[sl]=s1;k2[sl]=c1; }
                        else { v3[sl]=s1;k3[sl]=c1; }
                    }
                }
            }
        }
        __syncthreads();
    }

    float2* cand = (float2*)(base + 65536);
#pragma unroll
    for (int sl = 0; sl < 4; sl++) {
        int ql = mw * 32 + (sl >> 1) * 16 + (sl & 1) * 8 + (lane >> 2);
        int e = nw * 12 + (lane & 3) * 3;
        cand[ql * 48 + e]     = make_float2(v1[sl], __int_as_float(k1[sl]));
        cand[ql * 48 + e + 1] = make_float2(v2[sl], __int_as_float(k2[sl]));
        cand[ql * 48 + e + 2] = make_float2(v3[sl], __int_as_float(k3[sl]));
    }
    __syncthreads();
    if (t < MQ) {
        float m1 = __int_as_float(0x7f800000);
#pragma unroll
        for (int e = 0; e < 48; e++) m1 = fminf(m1, cand[t * 48 + e].x);
        float lim = m1 + WIN;
        int overflow = 0;
#pragma unroll
        for (int e = 2; e < 48; e += 3) overflow |= (cand[t * 48 + e].x <= lim);
        int q = q0 + t;
        int n = 0;
        if (!overflow) {
#pragma unroll
            for (int e = 0; e < 48; e++) {
                if ((e % 3) == 2) continue;
                float2 c = cand[t * 48 + e];
                if (c.x <= lim && n < MAXCAND) g_cand[q][n++] = __float_as_int(c.y);
                else if (c.x <= lim) overflow = 1;
            }
        }
        g_ncand[q] = overflow ? -1 : n;
    }
}

// ---------------- kernel 4: FUSED exact fixup + z_q writer ----------------
// Phase A: exact argmin per query (bitwise-proven chains).
// Phase B: coalesced gather (float4 row loads -> smem transpose) + NCHW write.
__global__ __launch_bounds__(256) void k_fixup_zq(const float* __restrict__ z,
                                                  const float* __restrict__ cb,
                                                  float* __restrict__ out, int write_idx) {
    __shared__ int sidx[MQ];
    __shared__ float smA[32][257];
    const int t = threadIdx.x, lane = t & 31, w = t >> 5;
    const int qb = blockIdx.x * MQ;
    const int b = qb >> 10, hw0 = qb & 1023;

    // ---- phase A: warp w resolves queries w*16 .. w*16+15 ----
    for (int j = 0; j < 16; j++) {
        int ql = w * 16 + j;
        int q = qb + ql;
        int n = g_ncand[q];
        const float* zr = g_ztf + (size_t)q * D_DIM;
        float z2v = g_z2[q];
        float bv = __int_as_float(0x7f800000); int bk = 0x7fffffff;
        if (n < 0) {
            // full rescan, coalesced via g_cbT, 4 exact chains for ILP (rare)
            for (int i = 0; i < 256; i += 4) {
                int ka = lane + i * 32, kb2 = ka + 32, kc = ka + 64, kd = ka + 96;
                float a0 = 0.f, a1 = 0.f, a2 = 0.f, a3 = 0.f;
                for (int d = 0; d < D_DIM; d++) {
                    float zv = zr[d];
                    const float* row = g_cbT + (size_t)d * K_CODES;
                    a0 = __fmaf_rn(zv, row[ka], a0);
                    a1 = __fmaf_rn(zv, row[kb2], a1);
                    a2 = __fmaf_rn(zv, row[kc], a2);
                    a3 = __fmaf_rn(zv, row[kd], a3);
                }
                float d0 = __fadd_rn(__fsub_rn(z2v, __fmul_rn(2.0f, a0)), g_c2[ka]);
                float d1 = __fadd_rn(__fsub_rn(z2v, __fmul_rn(2.0f, a1)), g_c2[kb2]);
                float d2 = __fadd_rn(__fsub_rn(z2v, __fmul_rn(2.0f, a2)), g_c2[kc]);
                float d3 = __fadd_rn(__fsub_rn(z2v, __fmul_rn(2.0f, a3)), g_c2[kd]);
                if (d0 < bv || (d0 == bv && ka < bk))  { bv = d0; bk = ka; }
                if (d1 < bv || (d1 == bv && kb2 < bk)) { bv = d1; bk = kb2; }
                if (d2 < bv || (d2 == bv && kc < bk))  { bv = d2; bk = kc; }
                if (d3 < bv || (d3 == bv && kd < bk))  { bv = d3; bk = kd; }
            }
        } else if (lane < n) {
            int k = g_cand[q][lane];
            float acc = 0.f;
#pragma unroll 8
            for (int d = 0; d < D_DIM; d++)
                acc = __fmaf_rn(zr[d], g_cbT[(size_t)d * K_CODES + k], acc);
            bv = __fadd_rn(__fsub_rn(z2v, __fmul_rn(2.0f, acc)), g_c2[k]);
            bk = k;
        }
#pragma unroll
        for (int o = 16; o; o >>= 1) {
            float ov = __shfl_xor_sync(0xffffffffu, bv, o);
            int   ok = __shfl_xor_sync(0xffffffffu, bk, o);
            if (ov < bv || (ov == bv && ok < bk)) { bv = ov; bk = ok; }
        }
        if (lane == 0) sidx[ql] = bk;
    }
    __syncthreads();
    if (t < MQ && write_idx) out[(size_t)N_Q * D_DIM + qb + t] = (float)sidx[t];

    // ---- phase B: 4 tiles of 32 queries ----
    for (int tile = 0; tile < 4; tile++) {
        // load 32 codebook rows coalesced (float4), stage transposed in smem
#pragma unroll
        for (int r = 0; r < 4; r++) {
            int qq = w * 4 + r;
            const float4* row = (const float4*)(cb + (size_t)sidx[tile * 32 + qq] * D_DIM);
            float4 v0 = row[lane];
            float4 v1 = row[lane + 32];
            int d0 = lane * 4;
            smA[qq][d0] = v0.x; smA[qq][d0 + 1] = v0.y; smA[qq][d0 + 2] = v0.z; smA[qq][d0 + 3] = v0.w;
            smA[qq][d0 + 128] = v1.x; smA[qq][d0 + 129] = v1.y; smA[qq][d0 + 130] = v1.z; smA[qq][d0 + 131] = v1.w;
        }
        __syncthreads();
        // write z_q: 32q x 256d, coalesced 128B stores, exact straight-through math
#pragma unroll 4
        for (int i = 0; i < 32; i++) {
            int idx = t + i * 256;
            int d = idx >> 5, qq = idx & 31;
            float cv = smA[qq][d];
            size_t o = (size_t)b * (D_DIM * HW) + (size_t)d * HW + hw0 + tile * 32 + qq;
            float zv = z[o];
            out[o] = __fadd_rn(zv, __fsub_rn(cv, zv));
        }
        __syncthreads();
    }
}

// ---------------- launch (4 launches; slot #4 = the fused suspect) ----------------
extern "C" void kernel_launch(void* const* d_in, const int* in_sizes, int n_in,
                              void* d_out, int out_size) {
    const float* z_e = (const float*)d_in[0];
    const float* cb  = (const float*)d_in[1];
    float* out = (float*)d_out;

    const size_t smem = 3 * 65536 + 1024;
    cudaFuncSetAttribute(k_mma, cudaFuncAttributeMaxDynamicSharedMemorySize, (int)smem);
    int write_idx = (out_size >= (int)(N_Q * D_DIM + N_Q)) ? 1 : 0;

    k_prep_code<<<5120, 256>>>(cb);
    k_prep_z<<<4160, 256>>>(z_e);
    k_mma<<<N_Q / MQ, 512, smem>>>();
    k_fixup_zq<<<N_Q / MQ, 256>>>(z_e, cb, out, write_idx);
}